// round 3
// baseline (speedup 1.0000x reference)
#include <cuda_runtime.h>
#include <math.h>

// Shapes
#define BATCH 16
#define CCH   256
#define HH    128
#define WW2   128
#define HWSZ  16384          // H*W
#define RED   64
#define MID   32
#define NHEADS 4
#define GRP   4
#define WS    8
#define NTOK  64             // WS*WS
#define NWIN  4096           // B * 16 * 16
#define ATT_SCALE 0.35355339059327373f   // (MID/NHEADS)^-0.5 = 8^-0.5

// Scratch (device globals: allocation-free)
__device__ float g_xred[BATCH * RED * HWSZ];   // 64 MB
__device__ float g_attn[BATCH * RED * HWSZ];   // 64 MB
__device__ float g_W1[RED * CCH];
__device__ float g_b1[RED];
__device__ float g_W2[CCH * RED];
__device__ float g_b2[CCH];

// ---------------------------------------------------------------------------
// Kernel 0: fold BNs + sigmoid(alpha) into in_proj / out_proj weights+bias
// ---------------------------------------------------------------------------
__global__ void k_prep(const float* __restrict__ gin,  const float* __restrict__ bin,
                       const float* __restrict__ min_, const float* __restrict__ vin,
                       const float* __restrict__ w_in, const float* __restrict__ w_out,
                       const float* __restrict__ gout, const float* __restrict__ bout,
                       const float* __restrict__ mout, const float* __restrict__ vout,
                       const float* __restrict__ alpha)
{
    int tid = threadIdx.x;
    float s = 1.f / (1.f + expf(-alpha[0]));

    // W1[o][c] = in_proj_w[o][c] * inv_in[c]
    for (int idx = tid; idx < RED * CCH; idx += 256) {
        int c = idx & (CCH - 1);
        float inv = gin[c] * rsqrtf(vin[c] + 1e-5f);
        g_W1[idx] = w_in[idx] * inv;
    }
    // b1[o] = sum_c in_proj_w[o][c] * (beta[c] - mean[c]*inv[c])
    if (tid < RED) {
        float acc = 0.f;
        for (int c = 0; c < CCH; c++) {
            float inv = gin[c] * rsqrtf(vin[c] + 1e-5f);
            acc += w_in[tid * CCH + c] * (bin[c] - min_[c] * inv);
        }
        g_b1[tid] = acc;
    }
    // W2[o][r] = s * inv_out[o] * out_proj_w[o][r]
    for (int idx = tid; idx < CCH * RED; idx += 256) {
        int o = idx >> 6;
        float inv = gout[o] * rsqrtf(vout[o] + 1e-5f);
        g_W2[idx] = s * inv * w_out[idx];
    }
    // b2[o] = s * (beta_out[o] - mean_out[o]*inv_out[o])
    if (tid < CCH) {
        float inv = gout[tid] * rsqrtf(vout[tid] + 1e-5f);
        g_b2[tid] = s * (bout[tid] - mout[tid] * inv);
    }
}

// ---------------------------------------------------------------------------
// Kernel 1: x_red = W1 @ x + b1     (M=64, K=256, N=262144)
// one block: 64 outputs x 128 contiguous spatial positions
// ---------------------------------------------------------------------------
__global__ __launch_bounds__(256) void k_inproj(const float* __restrict__ x)
{
    __shared__ float Wsm[64 * 64];    // [o][kk]
    __shared__ float Xsm[64 * 128];   // [kk][p]

    const int tid = threadIdx.x;
    const int pos0 = blockIdx.x * 128;
    const int b   = pos0 >> 14;
    const int rem = pos0 & (HWSZ - 1);
    const int tp = tid & 31;          // p = tp*4 + j
    const int to = tid >> 5;          // o = to*8 + i   (warp-uniform)

    float acc[8][4];
#pragma unroll
    for (int i = 0; i < 8; i++)
#pragma unroll
        for (int j = 0; j < 4; j++) acc[i][j] = 0.f;

    for (int k0 = 0; k0 < 256; k0 += 64) {
        // stage W tile (64x64) as float4
        {
            const float4* wg = (const float4*)g_W1;
            for (int idx = tid; idx < 1024; idx += 256) {
                int o = idx >> 4, kq = idx & 15;
                ((float4*)Wsm)[o * 16 + kq] = wg[o * 64 + (k0 >> 2) + kq];
            }
        }
        // stage X tile (64x128) as float4
        {
            const float4* xg = (const float4*)x;
            for (int idx = tid; idx < 2048; idx += 256) {
                int kk = idx >> 5, pq = idx & 31;
                ((float4*)Xsm)[kk * 32 + pq] =
                    xg[(((long)(b * CCH + k0 + kk)) * HWSZ + rem) / 4 + pq];
            }
        }
        __syncthreads();
#pragma unroll 4
        for (int k = 0; k < 64; k += 4) {
            float4 wv[8];
#pragma unroll
            for (int i = 0; i < 8; i++)
                wv[i] = *(const float4*)&Wsm[(to * 8 + i) * 64 + k];
#pragma unroll
            for (int kk = 0; kk < 4; kk++) {
                float4 xq = *(const float4*)&Xsm[(k + kk) * 128 + tp * 4];
#pragma unroll
                for (int i = 0; i < 8; i++) {
                    float w = (kk == 0) ? wv[i].x : (kk == 1) ? wv[i].y
                            : (kk == 2) ? wv[i].z : wv[i].w;
                    acc[i][0] += w * xq.x; acc[i][1] += w * xq.y;
                    acc[i][2] += w * xq.z; acc[i][3] += w * xq.w;
                }
            }
        }
        __syncthreads();
    }
#pragma unroll
    for (int i = 0; i < 8; i++) {
        int o = to * 8 + i;
        float bb = g_b1[o];
        float4 r = make_float4(acc[i][0] + bb, acc[i][1] + bb,
                               acc[i][2] + bb, acc[i][3] + bb);
        *(float4*)&g_xred[(long)(b * RED + o) * HWSZ + rem + tp * 4] = r;
    }
}

// ---------------------------------------------------------------------------
// Kernel 2: per-window attention.  One CTA per 8x8 window, 256 threads.
// ---------------------------------------------------------------------------
#define K2_SMEM_FLOATS 22240
__global__ __launch_bounds__(256) void k_attn(
    const float* __restrict__ wqk_g, const float* __restrict__ wqh_g,
    const float* __restrict__ qb_g,  const float* __restrict__ wkh_g,
    const float* __restrict__ kb_g,  const float* __restrict__ wv_g,
    const float* __restrict__ vb_g,  const float* __restrict__ wo_g,
    const float* __restrict__ ob_g)
{
    extern __shared__ float sm[];
    float* xw   = sm;             // 64x64 = 4096
    float* bse  = sm + 4096;      // 32x64 = 2048
    float* qs   = sm + 6144;      // 2048
    float* ks2  = sm + 8192;      // 2048
    float* vs   = sm + 10240;     // 2048
    float* S    = sm + 12288;     // 64x65 = 4160
    float* outs = sm + 16448;     // 2048
    float* wqk  = sm + 18496;     // 512
    float* wqh  = sm + 19008;     // 1024
    float* wkh  = sm + 20032;     // 1024
    float* wv   = sm + 21056;     // 512
    float* wo   = sm + 21568;     // 512
    float* bias = sm + 22080;     // 160: q 0-31, k 32-63, v 64-95, o 96-159

    const int tid = threadIdx.x;
    const int bw = blockIdx.x;
    const int b  = bw >> 8;
    const int hb = (bw >> 4) & 15;
    const int wb = bw & 15;

    // weights -> smem
    for (int i = tid; i < 512;  i += 256) wqk[i] = wqk_g[i];
    for (int i = tid; i < 1024; i += 256) wqh[i] = wqh_g[i];
    for (int i = tid; i < 1024; i += 256) wkh[i] = wkh_g[i];
    for (int i = tid; i < 512;  i += 256) wv[i]  = wv_g[i];
    for (int i = tid; i < 512;  i += 256) wo[i]  = wo_g[i];
    if (tid < 32)       bias[tid] = qb_g[tid];
    else if (tid < 64)  bias[tid] = kb_g[tid - 32];
    else if (tid < 96)  bias[tid] = vb_g[tid - 64];
    else if (tid < 160) bias[tid] = ob_g[tid - 96];

    // gather window tile: xw[c][n], n = ty*8+tx
    const long winbase = (long)(hb * 8) * 128 + wb * 8;
    for (int idx = tid; idx < 4096; idx += 256) {
        int c = idx >> 6, n = idx & 63;
        int ty = n >> 3, tx = n & 7;
        xw[idx] = g_xred[(long)(b * RED + c) * HWSZ + winbase + ty * 128 + tx];
    }
    __syncthreads();

    // base = grouped conv (64 -> 32), groups of (out 8, in 16)
    for (int e = tid; e < 2048; e += 256) {
        int m = e >> 6, n = e & 63;
        int g = m >> 3;
        const float* wr = &wqk[g * 128 + (m & 7) * 16];
        const float* xr = &xw[(g * 16) * 64 + n];
        float a = 0.f;
#pragma unroll
        for (int i = 0; i < 16; i++) a += wr[i] * xr[i * 64];
        bse[e] = a;
    }
    __syncthreads();

    // q, k (dense 32x32 on base), v (grouped on xw)
    for (int e = tid; e < 2048; e += 256) {
        int m = e >> 6, n = e & 63;
        const float* wr = &wqh[m * 32];
        float a = bias[m];
#pragma unroll
        for (int i = 0; i < 32; i++) a += wr[i] * bse[i * 64 + n];
        qs[e] = a;
        wr = &wkh[m * 32];
        a = bias[32 + m];
#pragma unroll
        for (int i = 0; i < 32; i++) a += wr[i] * bse[i * 64 + n];
        ks2[e] = a;
        int g = m >> 3;
        const float* wrv = &wv[g * 128 + (m & 7) * 16];
        a = bias[64 + m];
#pragma unroll
        for (int i = 0; i < 16; i++) a += wrv[i] * xw[(g * 16 + i) * 64 + n];
        vs[e] = a;
    }

    // per-head attention (head dim 8)
    for (int h = 0; h < NHEADS; h++) {
        __syncthreads();
        // scores S[i][j]
        for (int e = tid; e < 4096; e += 256) {
            int i = e >> 6, j = e & 63;
            float a = 0.f;
#pragma unroll
            for (int d = 0; d < 8; d++)
                a += qs[(h * 8 + d) * 64 + i] * ks2[(h * 8 + d) * 64 + j];
            S[i * 65 + j] = a * ATT_SCALE;
        }
        __syncthreads();
        // softmax per row
        if (tid < 64) {
            float mx = -1e30f;
#pragma unroll
            for (int j = 0; j < 64; j++) mx = fmaxf(mx, S[tid * 65 + j]);
            float sum = 0.f;
#pragma unroll
            for (int j = 0; j < 64; j++) {
                float ev = expf(S[tid * 65 + j] - mx);
                S[tid * 65 + j] = ev; sum += ev;
            }
            float r = 1.f / sum;
#pragma unroll
            for (int j = 0; j < 64; j++) S[tid * 65 + j] *= r;
        }
        __syncthreads();
        // out = attn @ v   (8 channels x 64 tokens)
        for (int e = tid; e < 512; e += 256) {
            int i = e & 63, d = e >> 6;
            const float* vr = &vs[(h * 8 + d) * 64];
            float a = 0.f;
#pragma unroll
            for (int j = 0; j < 64; j++) a += S[i * 65 + j] * vr[j];
            outs[(h * 8 + d) * 64 + i] = a;
        }
    }
    __syncthreads();

    // o grouped conv (32 -> 64) + scatter back to NCHW
    for (int e = tid; e < 4096; e += 256) {
        int r = e >> 6, n = e & 63;
        int g = r >> 4;
        const float* wr = &wo[g * 128 + (r & 15) * 8];
        float a = bias[96 + r];
#pragma unroll
        for (int m = 0; m < 8; m++) a += wr[m] * outs[(g * 8 + m) * 64 + n];
        int ty = n >> 3, tx = n & 7;
        g_attn[(long)(b * RED + r) * HWSZ + winbase + ty * 128 + tx] = a;
    }
}

// ---------------------------------------------------------------------------
// Kernel 3: out = x + (W2 @ a + b2)   (M=256 in 4 o-tiles, K=64, N=262144)
// ---------------------------------------------------------------------------
__global__ __launch_bounds__(256) void k_outproj(const float* __restrict__ x,
                                                 float* __restrict__ out)
{
    __shared__ float Wsm[64 * 64];    // [o][kk]
    __shared__ float Xsm[64 * 128];   // [kk][p]

    const int tid = threadIdx.x;
    const int pos0 = blockIdx.x * 128;
    const int b   = pos0 >> 14;
    const int rem = pos0 & (HWSZ - 1);
    const int ot  = blockIdx.y;       // 0..3
    const int tp = tid & 31;
    const int to = tid >> 5;

    for (int idx = tid; idx < 1024; idx += 256)
        ((float4*)Wsm)[idx] = ((const float4*)g_W2)[ot * 1024 + idx];
    for (int idx = tid; idx < 2048; idx += 256) {
        int kk = idx >> 5, pq = idx & 31;
        ((float4*)Xsm)[idx] =
            ((const float4*)g_attn)[(((long)(b * RED + kk)) * HWSZ + rem) / 4 + pq];
    }
    __syncthreads();

    float acc[8][4];
#pragma unroll
    for (int i = 0; i < 8; i++)
#pragma unroll
        for (int j = 0; j < 4; j++) acc[i][j] = 0.f;

#pragma unroll 4
    for (int k = 0; k < 64; k += 4) {
        float4 wv[8];
#pragma unroll
        for (int i = 0; i < 8; i++)
            wv[i] = *(const float4*)&Wsm[(to * 8 + i) * 64 + k];
#pragma unroll
        for (int kk = 0; kk < 4; kk++) {
            float4 xq = *(const float4*)&Xsm[(k + kk) * 128 + tp * 4];
#pragma unroll
            for (int i = 0; i < 8; i++) {
                float w = (kk == 0) ? wv[i].x : (kk == 1) ? wv[i].y
                        : (kk == 2) ? wv[i].z : wv[i].w;
                acc[i][0] += w * xq.x; acc[i][1] += w * xq.y;
                acc[i][2] += w * xq.z; acc[i][3] += w * xq.w;
            }
        }
    }

#pragma unroll
    for (int i = 0; i < 8; i++) {
        int o = ot * 64 + to * 8 + i;
        float bb = g_b2[o];
        long gaddr = (long)(b * CCH + o) * HWSZ + rem + tp * 4;
        float4 xi = *(const float4*)&x[gaddr];
        float4 r = make_float4(acc[i][0] + bb + xi.x, acc[i][1] + bb + xi.y,
                               acc[i][2] + bb + xi.z, acc[i][3] + bb + xi.w);
        *(float4*)&out[gaddr] = r;
    }
}

// ---------------------------------------------------------------------------
extern "C" void kernel_launch(void* const* d_in, const int* in_sizes, int n_in,
                              void* d_out, int out_size)
{
    const float* x            = (const float*)d_in[0];
    const float* bn_in_gamma  = (const float*)d_in[1];
    const float* bn_in_beta   = (const float*)d_in[2];
    const float* bn_in_mean   = (const float*)d_in[3];
    const float* bn_in_var    = (const float*)d_in[4];
    const float* in_proj_w    = (const float*)d_in[5];
    const float* qk_base_w    = (const float*)d_in[6];
    const float* q_head_w     = (const float*)d_in[7];
    const float* q_head_b     = (const float*)d_in[8];
    const float* k_head_w     = (const float*)d_in[9];
    const float* k_head_b     = (const float*)d_in[10];
    const float* v_w          = (const float*)d_in[11];
    const float* v_b          = (const float*)d_in[12];
    const float* o_w          = (const float*)d_in[13];
    const float* o_b          = (const float*)d_in[14];
    const float* out_proj_w   = (const float*)d_in[15];
    const float* bn_out_gamma = (const float*)d_in[16];
    const float* bn_out_beta  = (const float*)d_in[17];
    const float* bn_out_mean  = (const float*)d_in[18];
    const float* bn_out_var   = (const float*)d_in[19];
    const float* alpha        = (const float*)d_in[20];

    float* out = (float*)d_out;

    k_prep<<<1, 256>>>(bn_in_gamma, bn_in_beta, bn_in_mean, bn_in_var,
                       in_proj_w, out_proj_w,
                       bn_out_gamma, bn_out_beta, bn_out_mean, bn_out_var,
                       alpha);

    k_inproj<<<2048, 256>>>(x);

    static_assert(K2_SMEM_FLOATS * 4 < 228 * 1024, "smem");
    cudaFuncSetAttribute(k_attn, cudaFuncAttributeMaxDynamicSharedMemorySize,
                         K2_SMEM_FLOATS * 4);
    k_attn<<<NWIN, 256, K2_SMEM_FLOATS * 4>>>(qk_base_w, q_head_w, q_head_b,
                                              k_head_w, k_head_b,
                                              v_w, v_b, o_w, o_b);

    k_outproj<<<dim3(2048, 4), 256>>>(x, out);
}

// round 4
// speedup vs baseline: 1.0161x; 1.0161x over previous
#include <cuda_runtime.h>
#include <math.h>

#define BATCH 16
#define CCH   256
#define HWSZ  16384
#define RED   64
#define MID   32
#define NWIN  4096
#define ATT_SCALE 0.35355339059327373f   // 8^-0.5

// Folded weights (prepared by k_prep)
__device__ float g_W1t[CCH * RED];   // [c][o]   W1[o][c]*inv_in[c]
__device__ float g_b1[RED];
__device__ float g_W2t[RED * CCH];   // [r][o]   s*inv_out[o]*W2[o][r]
__device__ float g_b2[CCH];

typedef unsigned long long u64t;
__device__ __forceinline__ u64t pk(float a) {
    u64t r; asm("mov.b64 %0, {%1,%1};" : "=l"(r) : "f"(a)); return r;
}
__device__ __forceinline__ void f2fma(u64t& d, u64t a, u64t b) {
    asm("fma.rn.f32x2 %0, %1, %2, %0;" : "+l"(d) : "l"(a), "l"(b));
}
__device__ __forceinline__ float2 up(u64t a) {
    float2 f; asm("mov.b64 {%0, %1}, %2;" : "=f"(f.x), "=f"(f.y) : "l"(a)); return f;
}

// ---------------------------------------------------------------------------
// k_prep: fold BNs + sigmoid(alpha) into transposed projection weights
// ---------------------------------------------------------------------------
__global__ void k_prep(const float* __restrict__ gin,  const float* __restrict__ bin,
                       const float* __restrict__ min_, const float* __restrict__ vin,
                       const float* __restrict__ w_in, const float* __restrict__ w_out,
                       const float* __restrict__ gout, const float* __restrict__ bout,
                       const float* __restrict__ mout, const float* __restrict__ vout,
                       const float* __restrict__ alpha)
{
    int tid = threadIdx.x;
    float s = 1.f / (1.f + expf(-alpha[0]));

    for (int idx = tid; idx < CCH * RED; idx += 256) {
        int c = idx >> 6, o = idx & 63;
        float inv = gin[c] * rsqrtf(vin[c] + 1e-5f);
        g_W1t[idx] = w_in[o * CCH + c] * inv;
    }
    if (tid < RED) {
        float a = 0.f;
        for (int c = 0; c < CCH; c++) {
            float inv = gin[c] * rsqrtf(vin[c] + 1e-5f);
            a += w_in[tid * CCH + c] * (bin[c] - min_[c] * inv);
        }
        g_b1[tid] = a;
    }
    for (int idx = tid; idx < RED * CCH; idx += 256) {
        int r = idx >> 8, o = idx & 255;
        float inv = gout[o] * rsqrtf(vout[o] + 1e-5f);
        g_W2t[idx] = s * inv * w_out[o * RED + r];
    }
    if (tid < 256) {
        float inv = gout[tid] * rsqrtf(vout[tid] + 1e-5f);
        g_b2[tid] = s * (bout[tid] - mout[tid] * inv);
    }
}

// ---------------------------------------------------------------------------
// SMEM layout (float offsets). Regions reused across phases:
//   A: xchunk (in_proj) -> S (attention scores)
//   B: Wt staging (in_proj + out_proj)
//   C: xr (in_proj out, attention in) -> attout (o-conv out, out_proj in)
//   D: base -> outs
// ---------------------------------------------------------------------------
#define SM_A    0        // 4160
#define SM_B    4160     // 4096
#define SM_C    8256     // 4096
#define SM_D    12352    // 2048
#define SM_E    14400    // 2048  qs
#define SM_F    16448    // 2048  ks
#define SM_G    18496    // 2048  vs
#define SM_WQK  20544    // 512
#define SM_WQH  21056    // 1024
#define SM_WKH  22080    // 1024
#define SM_WV   23104    // 512
#define SM_WO   23616    // 512
#define SM_BQ   24128    // 32
#define SM_BK   24160    // 32
#define SM_BV   24192    // 32
#define SM_BO   24224    // 64
#define SM_B1   24288    // 64
#define SM_B2   24352    // 256
#define SM_TOTAL 24608   // floats = 98432 bytes -> 2 CTAs/SM

__global__ __launch_bounds__(256, 2) void k_fused(
    const float* __restrict__ x, float* __restrict__ out,
    const float* __restrict__ wqk_g, const float* __restrict__ wqh_g,
    const float* __restrict__ qb_g,  const float* __restrict__ wkh_g,
    const float* __restrict__ kb_g,  const float* __restrict__ wv_g,
    const float* __restrict__ vb_g,  const float* __restrict__ wo_g,
    const float* __restrict__ ob_g)
{
    extern __shared__ float sm[];
    const int tid = threadIdx.x;
    const int bw = blockIdx.x;
    const int b  = bw >> 8;
    const int hb = (bw >> 4) & 15;
    const int wb = bw & 15;
    const long winbase = (long)(hb * 8) * 128 + wb * 8;
    const long xwin = (long)b * CCH * HWSZ + winbase;

    // ---- phase 0: small weights to smem ----
    for (int i = tid; i < 512;  i += 256) sm[SM_WQK + i] = wqk_g[i];
    for (int i = tid; i < 1024; i += 256) sm[SM_WQH + i] = wqh_g[i];
    for (int i = tid; i < 1024; i += 256) sm[SM_WKH + i] = wkh_g[i];
    for (int i = tid; i < 512;  i += 256) sm[SM_WV + i]  = wv_g[i];
    for (int i = tid; i < 512;  i += 256) sm[SM_WO + i]  = wo_g[i];
    if (tid < 32)        sm[SM_BQ + tid]       = qb_g[tid];
    else if (tid < 64)   sm[SM_BK + tid - 32]  = kb_g[tid - 32];
    else if (tid < 96)   sm[SM_BV + tid - 64]  = vb_g[tid - 64];
    else if (tid < 160)  sm[SM_BO + tid - 96]  = ob_g[tid - 96];
    if (tid < 64)  sm[SM_B1 + tid] = g_b1[tid];
    sm[SM_B2 + tid] = g_b2[tid];

    const int to = tid >> 4, tn = tid & 15;
    const int o0 = to * 4, n0 = tn * 4;

    // ---- in_proj: xr[64][64] = W1t^T @ x_window, K=256 in 4 chunks ----
    u64t acc[2][4] = {{0ull,0ull,0ull,0ull},{0ull,0ull,0ull,0ull}};
    for (int kc = 0; kc < 4; kc++) {
        for (int idx = tid; idx < 1024; idx += 256)
            ((float4*)(sm + SM_B))[idx] = ((const float4*)(g_W1t + kc * 4096))[idx];
        for (int idx = tid; idx < 1024; idx += 256) {
            int c = idx >> 4, q = idx & 15;
            ((float4*)(sm + SM_A))[idx] =
                *(const float4*)&x[xwin + (long)(kc * 64 + c) * HWSZ + ((q >> 1) << 7) + ((q & 1) << 2)];
        }
        __syncthreads();
#pragma unroll 8
        for (int k = 0; k < 64; k++) {
            const u64t* wp = (const u64t*)(sm + SM_B + k * 64 + o0);
            u64t w0 = wp[0], w1 = wp[1];
            float4 xv = *(const float4*)(sm + SM_A + k * 64 + n0);
            u64t x0 = pk(xv.x), x1 = pk(xv.y), x2 = pk(xv.z), x3 = pk(xv.w);
            f2fma(acc[0][0], w0, x0); f2fma(acc[0][1], w0, x1);
            f2fma(acc[0][2], w0, x2); f2fma(acc[0][3], w0, x3);
            f2fma(acc[1][0], w1, x0); f2fma(acc[1][1], w1, x1);
            f2fma(acc[1][2], w1, x2); f2fma(acc[1][3], w1, x3);
        }
        __syncthreads();
    }
#pragma unroll
    for (int op = 0; op < 2; op++) {
        float ba = sm[SM_B1 + o0 + op * 2], bb = sm[SM_B1 + o0 + op * 2 + 1];
#pragma unroll
        for (int j = 0; j < 4; j++) {
            float2 v = up(acc[op][j]);
            sm[SM_C + (o0 + op * 2)     * 64 + n0 + j] = v.x + ba;
            sm[SM_C + (o0 + op * 2 + 1) * 64 + n0 + j] = v.y + bb;
        }
    }
    __syncthreads();

    // ---- base = grouped conv (64 -> 32) ----
    for (int e = tid; e < 2048; e += 256) {
        int m = e >> 6, n = e & 63, g = m >> 3;
        const float* wr  = sm + SM_WQK + g * 128 + (m & 7) * 16;
        const float* xrp = sm + SM_C + (g * 16) * 64 + n;
        float a = 0.f;
#pragma unroll
        for (int i = 0; i < 16; i++) a += wr[i] * xrp[i * 64];
        sm[SM_D + e] = a;
    }
    __syncthreads();

    // ---- q, k (dense, share base loads), v (grouped on xr) ----
    for (int e = tid; e < 2048; e += 256) {
        int m = e >> 6, n = e & 63;
        const float* wq = sm + SM_WQH + m * 32;
        const float* wk = sm + SM_WKH + m * 32;
        float aq = sm[SM_BQ + m], ak = sm[SM_BK + m];
#pragma unroll
        for (int i = 0; i < 32; i++) {
            float bb = sm[SM_D + i * 64 + n];
            aq += wq[i] * bb; ak += wk[i] * bb;
        }
        sm[SM_E + e] = aq; sm[SM_F + e] = ak;
        int g = m >> 3;
        const float* wvp = sm + SM_WV + g * 128 + (m & 7) * 16;
        float avv = sm[SM_BV + m];
#pragma unroll
        for (int i = 0; i < 16; i++) avv += wvp[i] * sm[SM_C + (g * 16 + i) * 64 + n];
        sm[SM_G + e] = avv;
    }
    __syncthreads();

    // ---- per-head attention ----
    for (int h = 0; h < 4; h++) {
        // scores, 4x4 register tile per thread
        {
            float sc[4][4];
#pragma unroll
            for (int a = 0; a < 4; a++)
#pragma unroll
                for (int c = 0; c < 4; c++) sc[a][c] = 0.f;
#pragma unroll
            for (int d = 0; d < 8; d++) {
                float4 q4 = *(const float4*)(sm + SM_E + (h * 8 + d) * 64 + o0);
                float4 k4 = *(const float4*)(sm + SM_F + (h * 8 + d) * 64 + n0);
                sc[0][0] += q4.x * k4.x; sc[0][1] += q4.x * k4.y; sc[0][2] += q4.x * k4.z; sc[0][3] += q4.x * k4.w;
                sc[1][0] += q4.y * k4.x; sc[1][1] += q4.y * k4.y; sc[1][2] += q4.y * k4.z; sc[1][3] += q4.y * k4.w;
                sc[2][0] += q4.z * k4.x; sc[2][1] += q4.z * k4.y; sc[2][2] += q4.z * k4.z; sc[2][3] += q4.z * k4.w;
                sc[3][0] += q4.w * k4.x; sc[3][1] += q4.w * k4.y; sc[3][2] += q4.w * k4.z; sc[3][3] += q4.w * k4.w;
            }
#pragma unroll
            for (int a = 0; a < 4; a++)
#pragma unroll
                for (int c = 0; c < 4; c++)
                    sm[SM_A + (o0 + a) * 65 + n0 + c] = sc[a][c] * ATT_SCALE;
        }
        __syncthreads();
        // softmax per row
        if (tid < 64) {
            float* Sr = sm + SM_A + tid * 65;
            float mx = -1e30f;
#pragma unroll
            for (int j = 0; j < 64; j++) mx = fmaxf(mx, Sr[j]);
            float sum = 0.f;
#pragma unroll
            for (int j = 0; j < 64; j++) { float ev = __expf(Sr[j] - mx); Sr[j] = ev; sum += ev; }
            float rcp = 1.f / sum;
#pragma unroll
            for (int j = 0; j < 64; j++) Sr[j] *= rcp;
        }
        __syncthreads();
        // out = attn @ v : each thread 2 rows (d, d+1) for one token i
        {
            int i = tid & 63, dq = tid >> 6;
            int r0 = h * 8 + dq * 2;
            float a0 = 0.f, a1 = 0.f;
            const float* Sr = sm + SM_A + i * 65;
#pragma unroll
            for (int j = 0; j < 64; j += 4) {
                float4 v0 = *(const float4*)(sm + SM_G + r0 * 64 + j);
                float4 v1 = *(const float4*)(sm + SM_G + (r0 + 1) * 64 + j);
                float s0 = Sr[j], s1 = Sr[j + 1], s2 = Sr[j + 2], s3 = Sr[j + 3];
                a0 += s0 * v0.x + s1 * v0.y + s2 * v0.z + s3 * v0.w;
                a1 += s0 * v1.x + s1 * v1.y + s2 * v1.z + s3 * v1.w;
            }
            sm[SM_D + r0 * 64 + i]       = a0;
            sm[SM_D + (r0 + 1) * 64 + i] = a1;
        }
        __syncthreads();
    }

    // ---- o grouped conv (32 -> 64) -> attout in C ----
    for (int e = tid; e < 4096; e += 256) {
        int r = e >> 6, n = e & 63, g = r >> 4;
        const float* wr = sm + SM_WO + g * 128 + (r & 15) * 8;
        float a = sm[SM_BO + r];
#pragma unroll
        for (int m = 0; m < 8; m++) a += wr[m] * sm[SM_D + (g * 8 + m) * 64 + n];
        sm[SM_C + e] = a;
    }
    __syncthreads();

    // ---- out_proj (256 outs in 4 tiles of 64, K=64) + residual + store ----
    const int ty0 = ((n0 >> 3) << 7);   // (n>>3)*128
    const int tx0 = (n0 & 7);
    for (int ot = 0; ot < 4; ot++) {
        for (int idx = tid; idx < 1024; idx += 256) {
            int r = idx >> 4, oq = idx & 15;
            ((float4*)(sm + SM_B))[idx] =
                *(const float4*)&g_W2t[r * 256 + ot * 64 + oq * 4];
        }
        __syncthreads();
        u64t a2[2][4] = {{0ull,0ull,0ull,0ull},{0ull,0ull,0ull,0ull}};
#pragma unroll 8
        for (int k = 0; k < 64; k++) {
            const u64t* wp = (const u64t*)(sm + SM_B + k * 64 + o0);
            u64t w0 = wp[0], w1 = wp[1];
            float4 xv = *(const float4*)(sm + SM_C + k * 64 + n0);
            u64t x0 = pk(xv.x), x1 = pk(xv.y), x2 = pk(xv.z), x3 = pk(xv.w);
            f2fma(a2[0][0], w0, x0); f2fma(a2[0][1], w0, x1);
            f2fma(a2[0][2], w0, x2); f2fma(a2[0][3], w0, x3);
            f2fma(a2[1][0], w1, x0); f2fma(a2[1][1], w1, x1);
            f2fma(a2[1][2], w1, x2); f2fma(a2[1][3], w1, x3);
        }
        float r4[4][4];
#pragma unroll
        for (int op = 0; op < 2; op++)
#pragma unroll
            for (int j = 0; j < 4; j++) {
                float2 v = up(a2[op][j]);
                r4[op * 2][j]     = v.x;
                r4[op * 2 + 1][j] = v.y;
            }
#pragma unroll
        for (int i2 = 0; i2 < 4; i2++) {
            int o = ot * 64 + o0 + i2;
            long ga = xwin + (long)o * HWSZ + ty0 + tx0;
            float4 xi = *(const float4*)&x[ga];
            float bb = sm[SM_B2 + o];
            float4 ov;
            ov.x = r4[i2][0] + bb + xi.x;
            ov.y = r4[i2][1] + bb + xi.y;
            ov.z = r4[i2][2] + bb + xi.z;
            ov.w = r4[i2][3] + bb + xi.w;
            *(float4*)&out[ga] = ov;
        }
        __syncthreads();
    }
}

// ---------------------------------------------------------------------------
extern "C" void kernel_launch(void* const* d_in, const int* in_sizes, int n_in,
                              void* d_out, int out_size)
{
    const float* x            = (const float*)d_in[0];
    const float* bn_in_gamma  = (const float*)d_in[1];
    const float* bn_in_beta   = (const float*)d_in[2];
    const float* bn_in_mean   = (const float*)d_in[3];
    const float* bn_in_var    = (const float*)d_in[4];
    const float* in_proj_w    = (const float*)d_in[5];
    const float* qk_base_w    = (const float*)d_in[6];
    const float* q_head_w     = (const float*)d_in[7];
    const float* q_head_b     = (const float*)d_in[8];
    const float* k_head_w     = (const float*)d_in[9];
    const float* k_head_b     = (const float*)d_in[10];
    const float* v_w          = (const float*)d_in[11];
    const float* v_b          = (const float*)d_in[12];
    const float* o_w          = (const float*)d_in[13];
    const float* o_b          = (const float*)d_in[14];
    const float* out_proj_w   = (const float*)d_in[15];
    const float* bn_out_gamma = (const float*)d_in[16];
    const float* bn_out_beta  = (const float*)d_in[17];
    const float* bn_out_mean  = (const float*)d_in[18];
    const float* bn_out_var   = (const float*)d_in[19];
    const float* alpha        = (const float*)d_in[20];

    float* out = (float*)d_out;

    k_prep<<<1, 256>>>(bn_in_gamma, bn_in_beta, bn_in_mean, bn_in_var,
                       in_proj_w, out_proj_w,
                       bn_out_gamma, bn_out_beta, bn_out_mean, bn_out_var,
                       alpha);

    cudaFuncSetAttribute(k_fused, cudaFuncAttributeMaxDynamicSharedMemorySize,
                         SM_TOTAL * 4);
    k_fused<<<NWIN, 256, SM_TOTAL * 4>>>(x, out,
                                         qk_base_w, q_head_w, q_head_b,
                                         k_head_w, k_head_b,
                                         v_w, v_b, o_w, o_b);
}

// round 5
// speedup vs baseline: 1.2627x; 1.2427x over previous
#include <cuda_runtime.h>
#include <math.h>

#define BATCH 16
#define CCH   256
#define HWSZ  16384
#define RED   64
#define MID   32
#define NWIN  4096
#define ATT_SCALE 0.35355339059327373f   // 8^-0.5

// Folded weights (prepared by k_prep)
__device__ float g_W1t[CCH * RED];   // [c][o]
__device__ float g_b1[RED];
__device__ float g_W2t[RED * CCH];   // [r][o]
__device__ float g_b2[CCH];
__device__ float g_Wqkt[MID * 64];   // [k][o]  o<32: q_head, o>=32: k_head
__device__ float g_bqk[64];

typedef unsigned long long u64t;
__device__ __forceinline__ u64t pk(float a) {
    u64t r; asm("mov.b64 %0, {%1,%1};" : "=l"(r) : "f"(a)); return r;
}
__device__ __forceinline__ void f2fma(u64t& d, u64t a, u64t b) {
    asm("fma.rn.f32x2 %0, %1, %2, %0;" : "+l"(d) : "l"(a), "l"(b));
}
__device__ __forceinline__ float2 up(u64t a) {
    float2 f; asm("mov.b64 {%0, %1}, %2;" : "=f"(f.x), "=f"(f.y) : "l"(a)); return f;
}

// ---------------------------------------------------------------------------
__global__ void k_prep(const float* __restrict__ gin,  const float* __restrict__ bin,
                       const float* __restrict__ min_, const float* __restrict__ vin,
                       const float* __restrict__ w_in, const float* __restrict__ w_out,
                       const float* __restrict__ gout, const float* __restrict__ bout,
                       const float* __restrict__ mout, const float* __restrict__ vout,
                       const float* __restrict__ alpha,
                       const float* __restrict__ qh,   const float* __restrict__ qb,
                       const float* __restrict__ kh,   const float* __restrict__ kb)
{
    int tid = threadIdx.x;
    float s = 1.f / (1.f + expf(-alpha[0]));

    for (int idx = tid; idx < CCH * RED; idx += 256) {
        int c = idx >> 6, o = idx & 63;
        float inv = gin[c] * rsqrtf(vin[c] + 1e-5f);
        g_W1t[idx] = w_in[o * CCH + c] * inv;
    }
    if (tid < RED) {
        float a = 0.f;
        for (int c = 0; c < CCH; c++) {
            float inv = gin[c] * rsqrtf(vin[c] + 1e-5f);
            a += w_in[tid * CCH + c] * (bin[c] - min_[c] * inv);
        }
        g_b1[tid] = a;
    }
    for (int idx = tid; idx < RED * CCH; idx += 256) {
        int r = idx >> 8, o = idx & 255;
        float inv = gout[o] * rsqrtf(vout[o] + 1e-5f);
        g_W2t[idx] = s * inv * w_out[o * RED + r];
    }
    if (tid < 256) {
        float inv = gout[tid] * rsqrtf(vout[tid] + 1e-5f);
        g_b2[tid] = s * (bout[tid] - mout[tid] * inv);
    }
    for (int idx = tid; idx < MID * 64; idx += 256) {
        int k = idx >> 6, o = idx & 63;
        g_Wqkt[idx] = (o < 32) ? qh[o * 32 + k] : kh[(o - 32) * 32 + k];
    }
    if (tid < 64) g_bqk[tid] = (tid < 32) ? qb[tid] : kb[tid - 32];
}

// ---------------------------------------------------------------------------
// SMEM layout (floats), phase-overlaid:
//   A: xchunk(4096) -> Wqkt stage(2048) -> S(64x68=4352)
//   B: W1 stage(4096) -> [qs|ks](4096) -> W2 stage(4096)
//   C: xr(4096) -> attout(4096)
//   D: base(2048) -> outs(2048)
//   U: vs(2048)
// ---------------------------------------------------------------------------
#define SM_A    0
#define SM_B    4352
#define SM_C    8448
#define SM_D    12544
#define SM_U    14592
#define SM_WQK  16640
#define SM_WV   17152
#define SM_WO   17664
#define SM_BQK  18176
#define SM_BV   18240
#define SM_BO   18272
#define SM_B1   18336
#define SM_B2   18400
#define SM_TOTAL 18656   // 74624 bytes -> 3 CTAs/SM

__global__ __launch_bounds__(256, 3) void k_fused(
    const float* __restrict__ x, float* __restrict__ out,
    const float* __restrict__ wqk_g, const float* __restrict__ wv_g,
    const float* __restrict__ vb_g,  const float* __restrict__ wo_g,
    const float* __restrict__ ob_g)
{
    extern __shared__ float sm[];
    const int tid = threadIdx.x;
    const int bw = blockIdx.x;
    const int b  = bw >> 8;
    const int hb = (bw >> 4) & 15;
    const int wb = bw & 15;
    const long winbase = (long)(hb * 8) * 128 + wb * 8;
    const long xwin = (long)b * CCH * HWSZ + winbase;

    // ---- weights to smem ----
    for (int i = tid; i < 512; i += 256) {
        sm[SM_WQK + i] = wqk_g[i];
        sm[SM_WV + i]  = wv_g[i];
        sm[SM_WO + i]  = wo_g[i];
    }
    if (tid < 64)       sm[SM_BQK + tid] = g_bqk[tid];
    else if (tid < 96)  sm[SM_BV + tid - 64] = vb_g[tid - 64];
    else if (tid < 160) sm[SM_BO + tid - 96] = ob_g[tid - 96];
    else if (tid < 224) sm[SM_B1 + tid - 160] = g_b1[tid - 160];
    sm[SM_B2 + tid] = g_b2[tid];

    const int to = tid >> 4, tn = tid & 15;
    const int o0 = to * 4, n0 = tn * 4;

    // ================= in_proj: xr = W1t^T @ x_window =================
    {
        u64t acc[2][4] = {{0ull,0ull,0ull,0ull},{0ull,0ull,0ull,0ull}};
        for (int kc = 0; kc < 4; kc++) {
            for (int idx = tid; idx < 1024; idx += 256)
                ((float4*)(sm + SM_B))[idx] = ((const float4*)(g_W1t + kc * 4096))[idx];
            for (int idx = tid; idx < 1024; idx += 256) {
                int c = idx >> 4, q = idx & 15;
                ((float4*)(sm + SM_A))[idx] =
                    *(const float4*)&x[xwin + (long)(kc * 64 + c) * HWSZ + ((q >> 1) << 7) + ((q & 1) << 2)];
            }
            __syncthreads();
#pragma unroll 8
            for (int k = 0; k < 64; k++) {
                const u64t* wp = (const u64t*)(sm + SM_B + k * 64 + o0);
                u64t w0 = wp[0], w1 = wp[1];
                float4 xv = *(const float4*)(sm + SM_A + k * 64 + n0);
                u64t x0 = pk(xv.x), x1 = pk(xv.y), x2 = pk(xv.z), x3 = pk(xv.w);
                f2fma(acc[0][0], w0, x0); f2fma(acc[0][1], w0, x1);
                f2fma(acc[0][2], w0, x2); f2fma(acc[0][3], w0, x3);
                f2fma(acc[1][0], w1, x0); f2fma(acc[1][1], w1, x1);
                f2fma(acc[1][2], w1, x2); f2fma(acc[1][3], w1, x3);
            }
            __syncthreads();
        }
        float r4[4][4];
#pragma unroll
        for (int op = 0; op < 2; op++)
#pragma unroll
            for (int j = 0; j < 4; j++) {
                float2 v = up(acc[op][j]);
                r4[op * 2][j] = v.x; r4[op * 2 + 1][j] = v.y;
            }
#pragma unroll
        for (int i2 = 0; i2 < 4; i2++) {
            float bb = sm[SM_B1 + o0 + i2];
            float4 ov = make_float4(r4[i2][0] + bb, r4[i2][1] + bb,
                                    r4[i2][2] + bb, r4[i2][3] + bb);
            *(float4*)(sm + SM_C + (o0 + i2) * 64 + n0) = ov;
        }
    }
    __syncthreads();

    // ====== base (wqk) + v (wv), combined pass over xr; stage Wqkt ======
    {
#pragma unroll
        for (int t2 = 0; t2 < 2; t2++) {
            int et = tid + 256 * t2;
            int m = et >> 4, nb = (et & 15) * 4, g = m >> 3;
            const float* wr1 = sm + SM_WQK + g * 128 + (m & 7) * 16;
            const float* wr2 = sm + SM_WV  + g * 128 + (m & 7) * 16;
            float bv = sm[SM_BV + m];
            float4 ab = make_float4(0.f, 0.f, 0.f, 0.f);
            float4 av = make_float4(bv, bv, bv, bv);
#pragma unroll
            for (int i = 0; i < 16; i++) {
                float w1 = wr1[i], w2 = wr2[i];
                float4 xv = *(const float4*)(sm + SM_C + (g * 16 + i) * 64 + nb);
                ab.x += w1 * xv.x; ab.y += w1 * xv.y; ab.z += w1 * xv.z; ab.w += w1 * xv.w;
                av.x += w2 * xv.x; av.y += w2 * xv.y; av.z += w2 * xv.z; av.w += w2 * xv.w;
            }
            *(float4*)(sm + SM_D + m * 64 + nb) = ab;
            *(float4*)(sm + SM_U + m * 64 + nb) = av;
        }
        // stage combined q/k weights into A (free after in_proj)
        for (int idx = tid; idx < 512; idx += 256)
            ((float4*)(sm + SM_A))[idx] = ((const float4*)g_Wqkt)[idx];
    }
    __syncthreads();

    // ========== q|k : dense 64x64, K=32 GEMM on base ==========
    {
        u64t acc[2][4] = {{0ull,0ull,0ull,0ull},{0ull,0ull,0ull,0ull}};
#pragma unroll 8
        for (int k = 0; k < 32; k++) {
            const u64t* wp = (const u64t*)(sm + SM_A + k * 64 + o0);
            u64t w0 = wp[0], w1 = wp[1];
            float4 xv = *(const float4*)(sm + SM_D + k * 64 + n0);
            u64t x0 = pk(xv.x), x1 = pk(xv.y), x2 = pk(xv.z), x3 = pk(xv.w);
            f2fma(acc[0][0], w0, x0); f2fma(acc[0][1], w0, x1);
            f2fma(acc[0][2], w0, x2); f2fma(acc[0][3], w0, x3);
            f2fma(acc[1][0], w1, x0); f2fma(acc[1][1], w1, x1);
            f2fma(acc[1][2], w1, x2); f2fma(acc[1][3], w1, x3);
        }
        float r4[4][4];
#pragma unroll
        for (int op = 0; op < 2; op++)
#pragma unroll
            for (int j = 0; j < 4; j++) {
                float2 v = up(acc[op][j]);
                r4[op * 2][j] = v.x; r4[op * 2 + 1][j] = v.y;
            }
        __syncthreads();   // A reused as S next; ensure all reads of A done
#pragma unroll
        for (int i2 = 0; i2 < 4; i2++) {
            float bb = sm[SM_BQK + o0 + i2];
            float4 ov = make_float4(r4[i2][0] + bb, r4[i2][1] + bb,
                                    r4[i2][2] + bb, r4[i2][3] + bb);
            *(float4*)(sm + SM_B + (o0 + i2) * 64 + n0) = ov;
        }
    }
    __syncthreads();

    // ================= attention, per head =================
    for (int h = 0; h < 4; h++) {
        // scores 4x4 register tile -> S (stride 68)
        {
            float sc[4][4];
#pragma unroll
            for (int a = 0; a < 4; a++)
#pragma unroll
                for (int c = 0; c < 4; c++) sc[a][c] = 0.f;
#pragma unroll
            for (int d = 0; d < 8; d++) {
                float4 q4 = *(const float4*)(sm + SM_B + (h * 8 + d) * 64 + o0);
                float4 k4 = *(const float4*)(sm + SM_B + 2048 + (h * 8 + d) * 64 + n0);
                sc[0][0] += q4.x * k4.x; sc[0][1] += q4.x * k4.y; sc[0][2] += q4.x * k4.z; sc[0][3] += q4.x * k4.w;
                sc[1][0] += q4.y * k4.x; sc[1][1] += q4.y * k4.y; sc[1][2] += q4.y * k4.z; sc[1][3] += q4.y * k4.w;
                sc[2][0] += q4.z * k4.x; sc[2][1] += q4.z * k4.y; sc[2][2] += q4.z * k4.z; sc[2][3] += q4.z * k4.w;
                sc[3][0] += q4.w * k4.x; sc[3][1] += q4.w * k4.y; sc[3][2] += q4.w * k4.z; sc[3][3] += q4.w * k4.w;
            }
#pragma unroll
            for (int a = 0; a < 4; a++) {
                float4 ov = make_float4(sc[a][0] * ATT_SCALE, sc[a][1] * ATT_SCALE,
                                        sc[a][2] * ATT_SCALE, sc[a][3] * ATT_SCALE);
                *(float4*)(sm + SM_A + (o0 + a) * 68 + n0) = ov;
            }
        }
        __syncthreads();
        // softmax: 4 threads per row, shfl reduce
        {
            int row = tid >> 2, qd = tid & 3;
            float* Sr = sm + SM_A + row * 68 + qd * 16;
            float4 v0 = *(float4*)(Sr + 0), v1 = *(float4*)(Sr + 4);
            float4 v2 = *(float4*)(Sr + 8), v3 = *(float4*)(Sr + 12);
            float mx = fmaxf(fmaxf(fmaxf(v0.x, v0.y), fmaxf(v0.z, v0.w)),
                             fmaxf(fmaxf(v1.x, v1.y), fmaxf(v1.z, v1.w)));
            mx = fmaxf(mx, fmaxf(fmaxf(fmaxf(v2.x, v2.y), fmaxf(v2.z, v2.w)),
                                 fmaxf(fmaxf(v3.x, v3.y), fmaxf(v3.z, v3.w))));
            mx = fmaxf(mx, __shfl_xor_sync(0xffffffffu, mx, 1));
            mx = fmaxf(mx, __shfl_xor_sync(0xffffffffu, mx, 2));
            v0.x = __expf(v0.x - mx); v0.y = __expf(v0.y - mx); v0.z = __expf(v0.z - mx); v0.w = __expf(v0.w - mx);
            v1.x = __expf(v1.x - mx); v1.y = __expf(v1.y - mx); v1.z = __expf(v1.z - mx); v1.w = __expf(v1.w - mx);
            v2.x = __expf(v2.x - mx); v2.y = __expf(v2.y - mx); v2.z = __expf(v2.z - mx); v2.w = __expf(v2.w - mx);
            v3.x = __expf(v3.x - mx); v3.y = __expf(v3.y - mx); v3.z = __expf(v3.z - mx); v3.w = __expf(v3.w - mx);
            float s = (v0.x + v0.y + v0.z + v0.w) + (v1.x + v1.y + v1.z + v1.w)
                    + (v2.x + v2.y + v2.z + v2.w) + (v3.x + v3.y + v3.z + v3.w);
            s += __shfl_xor_sync(0xffffffffu, s, 1);
            s += __shfl_xor_sync(0xffffffffu, s, 2);
            float r = 1.f / s;
            v0.x *= r; v0.y *= r; v0.z *= r; v0.w *= r;
            v1.x *= r; v1.y *= r; v1.z *= r; v1.w *= r;
            v2.x *= r; v2.y *= r; v2.z *= r; v2.w *= r;
            v3.x *= r; v3.y *= r; v3.z *= r; v3.w *= r;
            *(float4*)(Sr + 0) = v0;  *(float4*)(Sr + 4) = v1;
            *(float4*)(Sr + 8) = v2;  *(float4*)(Sr + 12) = v3;
        }
        __syncthreads();
        // out = attn @ v : thread -> token i, rows r0, r0+1
        {
            int i = tid & 63, dq = tid >> 6;
            int r0 = h * 8 + dq * 2;
            const float* Sr = sm + SM_A + i * 68;
            float a0 = 0.f, a1 = 0.f;
#pragma unroll
            for (int j = 0; j < 64; j += 4) {
                float4 s4 = *(const float4*)(Sr + j);
                float4 w0 = *(const float4*)(sm + SM_U + r0 * 64 + j);
                float4 w1 = *(const float4*)(sm + SM_U + (r0 + 1) * 64 + j);
                a0 += s4.x * w0.x + s4.y * w0.y + s4.z * w0.z + s4.w * w0.w;
                a1 += s4.x * w1.x + s4.y * w1.y + s4.z * w1.z + s4.w * w1.w;
            }
            sm[SM_D + r0 * 64 + i]       = a0;
            sm[SM_D + (r0 + 1) * 64 + i] = a1;
        }
        __syncthreads();
    }

    // ========== o grouped conv (32 -> 64) -> attout in C ==========
#pragma unroll
    for (int t4 = 0; t4 < 4; t4++) {
        int et = tid + 256 * t4;
        int r = et >> 4, nb = (et & 15) * 4, g = r >> 4;
        const float* wr = sm + SM_WO + g * 128 + (r & 15) * 8;
        float bo = sm[SM_BO + r];
        float4 a = make_float4(bo, bo, bo, bo);
#pragma unroll
        for (int m = 0; m < 8; m++) {
            float w = wr[m];
            float4 xv = *(const float4*)(sm + SM_D + (g * 8 + m) * 64 + nb);
            a.x += w * xv.x; a.y += w * xv.y; a.z += w * xv.z; a.w += w * xv.w;
        }
        *(float4*)(sm + SM_C + r * 64 + nb) = a;
    }
    __syncthreads();

    // ========== out_proj + residual + store ==========
    const int ty0 = ((n0 >> 3) << 7);
    const int tx0 = (n0 & 7);
    for (int ot = 0; ot < 4; ot++) {
        for (int idx = tid; idx < 1024; idx += 256) {
            int r = idx >> 4, oq = idx & 15;
            ((float4*)(sm + SM_B))[idx] =
                *(const float4*)&g_W2t[r * 256 + ot * 64 + oq * 4];
        }
        __syncthreads();
        u64t a2[2][4] = {{0ull,0ull,0ull,0ull},{0ull,0ull,0ull,0ull}};
#pragma unroll 8
        for (int k = 0; k < 64; k++) {
            const u64t* wp = (const u64t*)(sm + SM_B + k * 64 + o0);
            u64t w0 = wp[0], w1 = wp[1];
            float4 xv = *(const float4*)(sm + SM_C + k * 64 + n0);
            u64t x0 = pk(xv.x), x1 = pk(xv.y), x2 = pk(xv.z), x3 = pk(xv.w);
            f2fma(a2[0][0], w0, x0); f2fma(a2[0][1], w0, x1);
            f2fma(a2[0][2], w0, x2); f2fma(a2[0][3], w0, x3);
            f2fma(a2[1][0], w1, x0); f2fma(a2[1][1], w1, x1);
            f2fma(a2[1][2], w1, x2); f2fma(a2[1][3], w1, x3);
        }
        float r4[4][4];
#pragma unroll
        for (int op = 0; op < 2; op++)
#pragma unroll
            for (int j = 0; j < 4; j++) {
                float2 v = up(a2[op][j]);
                r4[op * 2][j] = v.x; r4[op * 2 + 1][j] = v.y;
            }
#pragma unroll
        for (int i2 = 0; i2 < 4; i2++) {
            int o = ot * 64 + o0 + i2;
            long ga = xwin + (long)o * HWSZ + ty0 + tx0;
            float4 xi = *(const float4*)&x[ga];
            float bb = sm[SM_B2 + o];
            float4 ov = make_float4(r4[i2][0] + bb + xi.x, r4[i2][1] + bb + xi.y,
                                    r4[i2][2] + bb + xi.z, r4[i2][3] + bb + xi.w);
            *(float4*)&out[ga] = ov;
        }
        __syncthreads();
    }
}

// ---------------------------------------------------------------------------
extern "C" void kernel_launch(void* const* d_in, const int* in_sizes, int n_in,
                              void* d_out, int out_size)
{
    const float* x            = (const float*)d_in[0];
    const float* bn_in_gamma  = (const float*)d_in[1];
    const float* bn_in_beta   = (const float*)d_in[2];
    const float* bn_in_mean   = (const float*)d_in[3];
    const float* bn_in_var    = (const float*)d_in[4];
    const float* in_proj_w    = (const float*)d_in[5];
    const float* qk_base_w    = (const float*)d_in[6];
    const float* q_head_w     = (const float*)d_in[7];
    const float* q_head_b     = (const float*)d_in[8];
    const float* k_head_w     = (const float*)d_in[9];
    const float* k_head_b     = (const float*)d_in[10];
    const float* v_w          = (const float*)d_in[11];
    const float* v_b          = (const float*)d_in[12];
    const float* o_w          = (const float*)d_in[13];
    const float* o_b          = (const float*)d_in[14];
    const float* out_proj_w   = (const float*)d_in[15];
    const float* bn_out_gamma = (const float*)d_in[16];
    const float* bn_out_beta  = (const float*)d_in[17];
    const float* bn_out_mean  = (const float*)d_in[18];
    const float* bn_out_var   = (const float*)d_in[19];
    const float* alpha        = (const float*)d_in[20];

    float* out = (float*)d_out;

    k_prep<<<1, 256>>>(bn_in_gamma, bn_in_beta, bn_in_mean, bn_in_var,
                       in_proj_w, out_proj_w,
                       bn_out_gamma, bn_out_beta, bn_out_mean, bn_out_var,
                       alpha, q_head_w, q_head_b, k_head_w, k_head_b);

    cudaFuncSetAttribute(k_fused, cudaFuncAttributeMaxDynamicSharedMemorySize,
                         SM_TOTAL * 4);
    k_fused<<<NWIN, 256, SM_TOTAL * 4>>>(x, out,
                                         qk_base_w, v_w, v_b, o_w, o_b);
}